// round 12
// baseline (speedup 1.0000x reference)
#include <cuda_runtime.h>
#include <cuda_bf16.h>
#include <cstdint>

// HashEmbedding gather: out[row,:] = embedding[hashed_ids[row],:]
// rows = 32768, D = 1024 fp32 = 4096 B per row.
//
// R12: last untested cell of the width x hint matrix:
//   loads  = 256-bit ld.global.nc.L2::evict_last (pins 40MB table in L2,
//            half the gather wavefronts)
//   stores = 128-bit st.global.cs (proven best: v4+cs = 27.2us; v8
//            stores cost +1.2us regardless of hint)
// Structure: R8 champion shape — 256 threads, 4 sub-groups x 64 lanes,
// 2 rows per sub-group, int2 id fetch.

static constexpr int THREADS = 256;
static constexpr int LANES = 64;          // threads per row
static constexpr int ROWS_PER_BLK = 8;
static constexpr int ROW_BYTES = 4096;
static constexpr int D_F4 = 256;          // float4 per row

struct alignas(32) F8 { float4 lo, hi; };

__device__ __forceinline__ F8 ldg256_el(const char* p)
{
    F8 v;
    asm volatile("ld.global.nc.L2::evict_last.v8.f32 "
                 "{%0,%1,%2,%3,%4,%5,%6,%7}, [%8];"
                 : "=f"(v.lo.x), "=f"(v.lo.y), "=f"(v.lo.z), "=f"(v.lo.w),
                   "=f"(v.hi.x), "=f"(v.hi.y), "=f"(v.hi.z), "=f"(v.hi.w)
                 : "l"(p));
    return v;
}

__global__ void __launch_bounds__(THREADS)
hash_embedding_gather(const int* __restrict__ hashed_ids,
                      const char* __restrict__ emb,
                      float4* __restrict__ out,
                      int nrows)
{
    int t    = threadIdx.x;
    int sub  = t >> 6;        // 0..3
    int lane = t & 63;        // 0..63

    int row0 = blockIdx.x * ROWS_PER_BLK + sub * 2;
    if (row0 >= nrows) return;

    // One 8-byte load fetches both ids (row0 even -> 8B aligned).
    int2 ids = *reinterpret_cast<const int2*>(hashed_ids + row0);

    const char* srcA = emb + (size_t)ids.x * ROW_BYTES + lane * 32;
    const char* srcB = emb + (size_t)ids.y * ROW_BYTES + lane * 32;
    float4* __restrict__ dstA = out + (size_t)row0       * D_F4;
    float4* __restrict__ dstB = out + (size_t)(row0 + 1) * D_F4;

    // 4 independent 32B gathers (same 128B/thread, half the wavefronts).
    F8 a0 = ldg256_el(srcA);
    F8 a1 = ldg256_el(srcA + LANES * 32);
    F8 b0 = ldg256_el(srcB);
    F8 b1 = ldg256_el(srcB + LANES * 32);

    // 128-bit evict-first stores: proven-best store path.
    // lane*32B = float4 index lane*2; second v8 block at +LANES*2.
    int fi = lane * 2;
    __stcs(dstA + fi,                 a0.lo);
    __stcs(dstA + fi + 1,             a0.hi);
    __stcs(dstA + fi + LANES * 2,     a1.lo);
    __stcs(dstA + fi + LANES * 2 + 1, a1.hi);
    __stcs(dstB + fi,                 b0.lo);
    __stcs(dstB + fi + 1,             b0.hi);
    __stcs(dstB + fi + LANES * 2,     b1.lo);
    __stcs(dstB + fi + LANES * 2 + 1, b1.hi);
}

extern "C" void kernel_launch(void* const* d_in, const int* in_sizes, int n_in,
                              void* d_out, int out_size)
{
    // metadata order: input_ids (unused), hashed_ids (int32), embedding (fp32)
    const int*  hashed_ids = (const int*)d_in[1];
    const char* emb        = (const char*)d_in[2];
    float4*     out        = (float4*)d_out;

    int nrows = in_sizes[1];   // 32768
    int blocks = (nrows + ROWS_PER_BLK - 1) / ROWS_PER_BLK;

    hash_embedding_gather<<<blocks, THREADS>>>(hashed_ids, emb, out, nrows);
}

// round 13
// speedup vs baseline: 1.3465x; 1.3465x over previous
#include <cuda_runtime.h>
#include <cuda_bf16.h>
#include <cstdint>

// HashEmbedding gather: out[row,:] = embedding[hashed_ids[row],:]
// rows = 32768, D = 1024 fp32 = 256 float4 per row.
//
// FINAL (champion config, best measured: kernel 27.3us / bench 29.18us).
// 256-thread blocks, 4 sub-groups of 64 lanes, 2 rows per sub-group
// (8 rows/block, grid 4096). Per thread: one int2 id fetch (amortizes
// the dependent id-load over 2 rows), 8 independent float4 gathers
// front-batched (MLP=8), then 8 contiguous 128-bit evict-first stores.
//
// Why this is the floor (12-round evidence):
//  - DRAM traffic == the 134MB write stream (reads are L2-served;
//    table 40MB << 126MB L2). Measured write ceiling ~4.8 TB/s.
//  - Six structural families (MLP 2-8, persistent SW pipeline, TMA
//    bulk DMA, bucket dedup with 35% less LTS traffic, store width x
//    cache-hint matrix) all converge at 27.2-28.5us; dedup with LESS
//    traffic ran slower -> not LTS-bound, not issue-bound (<=5%),
//    not occupancy-bound (~80%). Pure DRAM-write-stream bound.
//  - .cs (evict-first) on 128-bit stores is worth ~1.2us vs plain/wt;
//    256-bit stores cost ~1.2us regardless of hint; splitting 32B
//    register blocks into stride-32B v4 stores breaks per-instruction
//    line coverage and write-amplifies (R12: 40us).

static constexpr int D_F4 = 256;          // float4 per row
static constexpr int THREADS = 256;
static constexpr int LANES = 64;          // threads per row
static constexpr int ROWS_PER_BLK = 8;    // 4 sub-groups x 2 rows

__global__ void __launch_bounds__(THREADS)
hash_embedding_gather(const int* __restrict__ hashed_ids,
                      const float4* __restrict__ emb,
                      float4* __restrict__ out,
                      int nrows)
{
    int t    = threadIdx.x;
    int sub  = t >> 6;        // 0..3
    int lane = t & 63;        // 0..63

    int row0 = blockIdx.x * ROWS_PER_BLK + sub * 2;
    if (row0 >= nrows) return;

    // One 8-byte load fetches both ids (row0 even -> 8B aligned).
    int2 ids = *reinterpret_cast<const int2*>(hashed_ids + row0);

    const float4* __restrict__ srcA = emb + (size_t)ids.x * D_F4;
    const float4* __restrict__ srcB = emb + (size_t)ids.y * D_F4;
    float4*       __restrict__ dstA = out + (size_t)row0       * D_F4;
    float4*       __restrict__ dstB = out + (size_t)(row0 + 1) * D_F4;

    // 8 independent gathers, front-batched (MLP=8 per thread).
    float4 a0 = __ldg(srcA + lane);
    float4 a1 = __ldg(srcA + lane + LANES);
    float4 a2 = __ldg(srcA + lane + 2 * LANES);
    float4 a3 = __ldg(srcA + lane + 3 * LANES);
    float4 b0 = __ldg(srcB + lane);
    float4 b1 = __ldg(srcB + lane + LANES);
    float4 b2 = __ldg(srcB + lane + 2 * LANES);
    float4 b3 = __ldg(srcB + lane + 3 * LANES);

    // Evict-first 128-bit stores: contiguous per instruction (lane-major),
    // full 128B line coverage; keeps the table resident in L2.
    __stcs(dstA + lane,             a0);
    __stcs(dstA + lane + LANES,     a1);
    __stcs(dstA + lane + 2 * LANES, a2);
    __stcs(dstA + lane + 3 * LANES, a3);
    __stcs(dstB + lane,             b0);
    __stcs(dstB + lane + LANES,     b1);
    __stcs(dstB + lane + 2 * LANES, b2);
    __stcs(dstB + lane + 3 * LANES, b3);
}

extern "C" void kernel_launch(void* const* d_in, const int* in_sizes, int n_in,
                              void* d_out, int out_size)
{
    // metadata order: input_ids (unused), hashed_ids (int32), embedding (fp32)
    const int*    hashed_ids = (const int*)d_in[1];
    const float4* emb        = (const float4*)d_in[2];
    float4*       out        = (float4*)d_out;

    int nrows = in_sizes[1];   // 32768
    int blocks = (nrows + ROWS_PER_BLK - 1) / ROWS_PER_BLK;

    hash_embedding_gather<<<blocks, THREADS>>>(hashed_ids, emb, out, nrows);
}

// round 14
// speedup vs baseline: 1.4189x; 1.0537x over previous
#include <cuda_runtime.h>
#include <cuda_bf16.h>
#include <cstdint>

// HashEmbedding gather: out[row,:] = embedding[hashed_ids[row],:]
// rows = 32768, D = 1024 fp32 = 256 float4 per row.
//
// R14: warp-per-row variant of the champion. One warp owns one 4KB row:
//  - id load is warp-uniform (1 request + broadcast, UR path)
//  - 8 coalesced float4 gathers per lane (MLP=8, same as champion)
//  - 8 contiguous evict-first 128-bit stores (512B per instruction)
// 8 warps/block, grid 4096. Everything else identical to the measured
// floor config (v4 __ldg + v4 __stcs), which is DRAM-write-bound at
// ~4.8 TB/s (134MB output / ~27us kernel).

static constexpr int D_F4 = 256;          // float4 per row
static constexpr int THREADS = 256;       // 8 warps
static constexpr int ROWS_PER_BLK = 8;    // 1 row per warp

__global__ void __launch_bounds__(THREADS)
hash_embedding_gather(const int* __restrict__ hashed_ids,
                      const float4* __restrict__ emb,
                      float4* __restrict__ out,
                      int nrows)
{
    const int warp = threadIdx.x >> 5;
    const int lane = threadIdx.x & 31;

    const int row = blockIdx.x * ROWS_PER_BLK + warp;
    if (row >= nrows) return;

    // Warp-uniform id load: one address across the warp.
    const int id = __ldg(hashed_ids + row);

    const float4* __restrict__ src = emb + (size_t)id  * D_F4;
    float4*       __restrict__ dst = out + (size_t)row * D_F4;

    // 8 independent coalesced gathers, front-batched (MLP=8 per lane).
    float4 v0 = __ldg(src + lane);
    float4 v1 = __ldg(src + lane + 32);
    float4 v2 = __ldg(src + lane + 64);
    float4 v3 = __ldg(src + lane + 96);
    float4 v4 = __ldg(src + lane + 128);
    float4 v5 = __ldg(src + lane + 160);
    float4 v6 = __ldg(src + lane + 192);
    float4 v7 = __ldg(src + lane + 224);

    // Evict-first 128-bit stores, 512B contiguous per instruction.
    __stcs(dst + lane,       v0);
    __stcs(dst + lane + 32,  v1);
    __stcs(dst + lane + 64,  v2);
    __stcs(dst + lane + 96,  v3);
    __stcs(dst + lane + 128, v4);
    __stcs(dst + lane + 160, v5);
    __stcs(dst + lane + 192, v6);
    __stcs(dst + lane + 224, v7);
}

extern "C" void kernel_launch(void* const* d_in, const int* in_sizes, int n_in,
                              void* d_out, int out_size)
{
    // metadata order: input_ids (unused), hashed_ids (int32), embedding (fp32)
    const int*    hashed_ids = (const int*)d_in[1];
    const float4* emb        = (const float4*)d_in[2];
    float4*       out        = (float4*)d_out;

    int nrows = in_sizes[1];   // 32768
    int blocks = (nrows + ROWS_PER_BLK - 1) / ROWS_PER_BLK;

    hash_embedding_gather<<<blocks, THREADS>>>(hashed_ids, emb, out, nrows);
}